// round 4
// baseline (speedup 1.0000x reference)
#include <cuda_runtime.h>

#define B_ 8
#define C_ 32
#define H_ 256
#define W_ 256
#define FH_ 64
#define FW_ 64
#define P_ 25
#define HP_ 306   // H + 2*25

// Scratch: transposed input [B,H,W,C] and per-pixel sample coords [B,H,W,2]
__device__ float g_tin[B_ * H_ * W_ * C_];
__device__ float g_coords[B_ * H_ * W_ * 2];

// XLA:GPU lowers f32 divide to div.full.f32 (~2 ulp). The resize 'src'
// coordinate src = i*63/255 is the ONE place where that rounding error is
// amplified: it survives (src - floor(src)) undamped and is then scaled by
// 152.5 into the sample position. Bit-match XLA's division here.
__device__ __forceinline__ float div_full(float a, float b) {
    float r;
    asm("div.full.f32 %0, %1, %2;" : "=f"(r) : "f"(a), "f"(b));
    return r;
}

__device__ __forceinline__ void cubic_w(float t, float w[4]) {
    const float A = -0.75f;
    float x;
    x = t + 1.0f; w[0] = ((A * x - 5.0f * A) * x + 8.0f * A) * x - 4.0f * A;
    x = t;        w[1] = ((A + 2.0f) * x - (A + 3.0f)) * x * x + 1.0f;
    x = 1.0f - t; w[2] = ((A + 2.0f) * x - (A + 3.0f)) * x * x + 1.0f;
    x = 2.0f - t; w[3] = ((A * x - 5.0f * A) * x + 8.0f * A) * x - 4.0f * A;
}

// ---------------------------------------------------------------------------
// Kernel 1: per-pixel sample coordinates (bicubic flow upsample + grid math)
// ---------------------------------------------------------------------------
__global__ void coords_kernel(const float* __restrict__ flow) {
    int idx = blockIdx.x * blockDim.x + threadIdx.x;
    if (idx >= B_ * H_ * W_) return;
    int j = idx & (W_ - 1);
    int i = (idx >> 8) & (H_ - 1);
    int b = idx >> 16;

    // bicubic resize source coords (align_corners=True) — div.full to match XLA
    float sy = div_full((float)i * (float)(FH_ - 1), (float)(H_ - 1));
    float sx = div_full((float)j * (float)(FW_ - 1), (float)(W_ - 1));
    float fy0 = floorf(sy), fx0 = floorf(sx);
    float ty = sy - fy0, tx = sx - fx0;   // exact (Sterbenz)
    int iy0 = (int)fy0, ix0 = (int)fx0;
    float wy[4], wx[4];
    cubic_w(ty, wy);
    cubic_w(tx, wx);

    const float* f0 = flow + b * 2 * FH_ * FW_;   // channel 0: x-flow
    const float* f1 = f0 + FH_ * FW_;             // channel 1: y-flow

    int ry[4], rx[4];
#pragma unroll
    for (int m = 0; m < 4; m++) {
        int y = iy0 - 1 + m; ry[m] = min(max(y, 0), FH_ - 1);
        int x = ix0 - 1 + m; rx[m] = min(max(x, 0), FW_ - 1);
    }
    float accx = 0.0f, accy = 0.0f;
#pragma unroll
    for (int m = 0; m < 4; m++) {
        int rb = ry[m] * FW_;
#pragma unroll
        for (int n = 0; n < 4; n++) {
            float w = wy[m] * wx[n];
            int o = rb + rx[n];
            accx += w * __ldg(&f0[o]);
            accy += w * __ldg(&f1[o]);
        }
    }

    // grid math: xn = flow_x - gx256(j) + gx306(j+P); pix = (xn+1)*0.5*(HP-1)
    float gx256 = -1.0f + j * (2.0f / (float)(W_ - 1));
    float gy256 = -1.0f + i * (2.0f / (float)(H_ - 1));
    float gx306 = -1.0f + (j + P_) * (2.0f / (float)(HP_ - 1));
    float gy306 = -1.0f + (i + P_) * (2.0f / (float)(HP_ - 1));
    float xp = (accx - gx256 + gx306 + 1.0f) * (0.5f * (float)(HP_ - 1));
    float yp = (accy - gy256 + gy306 + 1.0f) * (0.5f * (float)(HP_ - 1));

    g_coords[idx * 2 + 0] = xp;
    g_coords[idx * 2 + 1] = yp;
}

// ---------------------------------------------------------------------------
// Kernel 2: transpose input [B,C,H,W] -> [B,H,W,C] so channels are a 128B line
// ---------------------------------------------------------------------------
__global__ __launch_bounds__(1024) void transpose_kernel(const float* __restrict__ inp) {
    __shared__ float s[32][33];
    int b = blockIdx.z;
    int h = blockIdx.y;
    int w0 = blockIdx.x * 32;
    int c = threadIdx.y;
    int w = w0 + threadIdx.x;

    s[threadIdx.y][threadIdx.x] = inp[(((b * C_ + c) * H_) + h) * W_ + w];
    __syncthreads();
    // write: channel = threadIdx.x (contiguous), w = w0 + threadIdx.y
    g_tin[((b * H_ + h) * W_ + (w0 + threadIdx.y)) * C_ + threadIdx.x] =
        s[threadIdx.x][threadIdx.y];
}

// ---------------------------------------------------------------------------
// Kernel 3: gather. warp = one (b,i,j) pixel, lanes = 32 channels.
// Every tap is ONE aligned 128B line. Bounds checks are warp-uniform.
// SMEM re-transpose for coalesced [B,C,H,W] stores.
// ---------------------------------------------------------------------------
__global__ __launch_bounds__(1024) void gather_kernel(float* __restrict__ out) {
    __shared__ float s[32][33];
    int b = blockIdx.z;
    int i = blockIdx.y;
    int jt = blockIdx.x;           // 8 groups of 32 j
    int warp = threadIdx.x >> 5;
    int lane = threadIdx.x & 31;
    int j = jt * 32 + warp;

    int pidx = ((b * H_) + i) * W_ + j;
    float xp = g_coords[pidx * 2 + 0];
    float yp = g_coords[pidx * 2 + 1];

    float fx = floorf(xp), fy = floorf(yp);
    float tx = xp - fx, ty = yp - fy;
    int ix = (int)fx, iy = (int)fy;
    float wx[4], wy[4];
    cubic_w(tx, wx);
    cubic_w(ty, wy);

    const float* base = g_tin + (size_t)b * (H_ * W_ * C_);
    float acc = 0.0f;
#pragma unroll
    for (int m = 0; m < 4; m++) {
        int yy = iy - 1 + m;
        if ((unsigned)yy < (unsigned)HP_) {
            int ys = min(max(yy - P_, 0), H_ - 1);
            const float* row = base + ys * (W_ * C_);
            float wym = wy[m];
#pragma unroll
            for (int n = 0; n < 4; n++) {
                int xx = ix - 1 + n;
                if ((unsigned)xx < (unsigned)HP_) {
                    int xs = min(max(xx - P_, 0), W_ - 1);
                    acc += (wym * wx[n]) * __ldg(&row[xs * C_ + lane]);
                }
            }
        }
    }

    // s[pixel_in_tile][channel]
    s[warp][lane] = acc;
    __syncthreads();
    // warp w writes channel c=w, 32 contiguous j
    out[(((b * C_ + warp) * H_) + i) * W_ + jt * 32 + lane] = s[lane][warp];
}

extern "C" void kernel_launch(void* const* d_in, const int* in_sizes, int n_in,
                              void* d_out, int out_size) {
    const float* input = (const float*)d_in[0];   // [8,32,256,256]
    const float* flow  = (const float*)d_in[1];   // [8,2,64,64]
    float* out = (float*)d_out;                   // [8,32,256,256]

    {
        int total = B_ * H_ * W_;
        coords_kernel<<<(total + 255) / 256, 256>>>(flow);
    }
    {
        dim3 grid(W_ / 32, H_, B_);
        dim3 block(32, 32);
        transpose_kernel<<<grid, block>>>(input);
    }
    {
        dim3 grid(W_ / 32, H_, B_);
        gather_kernel<<<grid, 1024>>>(out);
    }
}

// round 5
// speedup vs baseline: 1.6254x; 1.6254x over previous
#include <cuda_runtime.h>
#include <cuda_fp16.h>

#define B_ 8
#define C_ 32
#define H_ 256
#define W_ 256
#define FH_ 64
#define FW_ 64
#define P_ 25
#define HP_ 306   // H + 2*25

// Scratch: fp16 transposed input [B,H,W,C] (64B/pixel) + per-pixel coords
__device__ __align__(128) __half g_tin_h[B_ * H_ * W_ * C_];
__device__ float g_coords[B_ * H_ * W_ * 2];

// XLA:GPU lowers f32 divide to div.full.f32 (~2 ulp). The resize 'src'
// coordinate src = i*63/255 is the ONE place where that rounding error is
// amplified: it survives (src - floor(src)) undamped and is then scaled by
// 152.5 into the sample position. Bit-match XLA's division here. (R3->R4:
// rel_err 1.76e-3 -> 1.24e-4.) DO NOT replace with __fdiv_rn or fast div.
__device__ __forceinline__ float div_full(float a, float b) {
    float r;
    asm("div.full.f32 %0, %1, %2;" : "=f"(r) : "f"(a), "f"(b));
    return r;
}

__device__ __forceinline__ void cubic_w(float t, float w[4]) {
    const float A = -0.75f;
    float x;
    x = t + 1.0f; w[0] = ((A * x - 5.0f * A) * x + 8.0f * A) * x - 4.0f * A;
    x = t;        w[1] = ((A + 2.0f) * x - (A + 3.0f)) * x * x + 1.0f;
    x = 1.0f - t; w[2] = ((A + 2.0f) * x - (A + 3.0f)) * x * x + 1.0f;
    x = 2.0f - t; w[3] = ((A * x - 5.0f * A) * x + 8.0f * A) * x - 4.0f * A;
}

// ---------------------------------------------------------------------------
// Kernel 1: per-pixel sample coordinates (bicubic flow upsample + grid math)
// ---------------------------------------------------------------------------
__global__ void coords_kernel(const float* __restrict__ flow) {
    int idx = blockIdx.x * blockDim.x + threadIdx.x;
    if (idx >= B_ * H_ * W_) return;
    int j = idx & (W_ - 1);
    int i = (idx >> 8) & (H_ - 1);
    int b = idx >> 16;

    float sy = div_full((float)i * (float)(FH_ - 1), (float)(H_ - 1));
    float sx = div_full((float)j * (float)(FW_ - 1), (float)(W_ - 1));
    float fy0 = floorf(sy), fx0 = floorf(sx);
    float ty = sy - fy0, tx = sx - fx0;   // exact (Sterbenz)
    int iy0 = (int)fy0, ix0 = (int)fx0;
    float wy[4], wx[4];
    cubic_w(ty, wy);
    cubic_w(tx, wx);

    const float* f0 = flow + b * 2 * FH_ * FW_;   // channel 0: x-flow
    const float* f1 = f0 + FH_ * FW_;             // channel 1: y-flow

    int ry[4], rx[4];
#pragma unroll
    for (int m = 0; m < 4; m++) {
        int y = iy0 - 1 + m; ry[m] = min(max(y, 0), FH_ - 1);
        int x = ix0 - 1 + m; rx[m] = min(max(x, 0), FW_ - 1);
    }
    float accx = 0.0f, accy = 0.0f;
#pragma unroll
    for (int m = 0; m < 4; m++) {
        int rb = ry[m] * FW_;
#pragma unroll
        for (int n = 0; n < 4; n++) {
            float w = wy[m] * wx[n];
            int o = rb + rx[n];
            accx += w * __ldg(&f0[o]);
            accy += w * __ldg(&f1[o]);
        }
    }

    float gx256 = -1.0f + j * (2.0f / (float)(W_ - 1));
    float gy256 = -1.0f + i * (2.0f / (float)(H_ - 1));
    float gx306 = -1.0f + (j + P_) * (2.0f / (float)(HP_ - 1));
    float gy306 = -1.0f + (i + P_) * (2.0f / (float)(HP_ - 1));
    float xp = (accx - gx256 + gx306 + 1.0f) * (0.5f * (float)(HP_ - 1));
    float yp = (accy - gy256 + gy306 + 1.0f) * (0.5f * (float)(HP_ - 1));

    g_coords[idx * 2 + 0] = xp;
    g_coords[idx * 2 + 1] = yp;
}

// ---------------------------------------------------------------------------
// Kernel 2: transpose input [B,C,H,W] f32 -> [B,H,W,C] f16 (64B per pixel)
// ---------------------------------------------------------------------------
__global__ __launch_bounds__(1024) void transpose_kernel(const float* __restrict__ inp) {
    __shared__ float s[32][33];
    int b = blockIdx.z;
    int h = blockIdx.y;
    int w0 = blockIdx.x * 32;

    // load: threadIdx.y = channel, threadIdx.x = w (coalesced 128B rows)
    s[threadIdx.y][threadIdx.x] =
        inp[(((b * C_ + threadIdx.y) * H_) + h) * W_ + w0 + threadIdx.x];
    __syncthreads();
    // store: threadIdx.x = channel (contiguous halfs), threadIdx.y = w
    g_tin_h[((b * H_ + h) * W_ + (w0 + threadIdx.y)) * C_ + threadIdx.x] =
        __float2half_rn(s[threadIdx.x][threadIdx.y]);
}

// ---------------------------------------------------------------------------
// Kernel 3: gather. warp = FOUR pixels (8 lanes each); lane = 4 channels via
// one uint2 (4 halfs) per tap. 4x fewer LDGs than 1-pixel/warp, same
// wavefront count; OOB taps predicated off (no traffic). Warp-wide early-out
// for fully-OOB warps. Conflict-free SMEM re-transpose for coalesced stores.
// ---------------------------------------------------------------------------
#define GW_ 64   // pixels per block (16 warps * 4)
__global__ __launch_bounds__(512) void gather_kernel(float* __restrict__ out) {
    __shared__ float s[C_][GW_ + 1];
    int b = blockIdx.z;
    int i = blockIdx.y;
    int jt = blockIdx.x;                 // 4 tiles of 64 j
    int warp = threadIdx.x >> 5;         // 0..15
    int lane = threadIdx.x & 31;
    int sub = lane >> 3;                 // pixel-in-warp 0..3
    int lane8 = lane & 7;                // channel-group 0..7
    int p = warp * 4 + sub;              // pixel-in-block 0..63
    int j = jt * GW_ + p;

    int pidx = ((b * H_) + i) * W_ + j;
    float xp = __ldg(&g_coords[pidx * 2 + 0]);
    float yp = __ldg(&g_coords[pidx * 2 + 1]);

    float fx = floorf(xp), fy = floorf(yp);
    float tx = xp - fx, ty = yp - fy;
    int ix = (int)fx, iy = (int)fy;

    float a0 = 0.0f, a1 = 0.0f, a2 = 0.0f, a3 = 0.0f;

    bool dead = (iy + 2 < 0) | (iy - 1 >= HP_) | (ix + 2 < 0) | (ix - 1 >= HP_);
    if (!__all_sync(0xFFFFFFFFu, dead)) {
        float wx[4], wy[4];
        cubic_w(tx, wx);
        cubic_w(ty, wy);

        const __half* base = g_tin_h + (size_t)b * (H_ * W_ * C_) + lane8 * 4;
#pragma unroll
        for (int m = 0; m < 4; m++) {
            int yy = iy - 1 + m;
            if ((unsigned)yy < (unsigned)HP_) {
                int ys = min(max(yy - P_, 0), H_ - 1);
                const __half* row = base + ys * (W_ * C_);
                float wym = wy[m];
#pragma unroll
                for (int n = 0; n < 4; n++) {
                    int xx = ix - 1 + n;
                    if ((unsigned)xx < (unsigned)HP_) {
                        int xs = min(max(xx - P_, 0), W_ - 1);
                        uint2 v = __ldg((const uint2*)(row + xs * C_));
                        float2 f01 = __half22float2(*(const __half2*)&v.x);
                        float2 f23 = __half22float2(*(const __half2*)&v.y);
                        float w = wym * wx[n];
                        a0 += w * f01.x;
                        a1 += w * f01.y;
                        a2 += w * f23.x;
                        a3 += w * f23.y;
                    }
                }
            }
        }
    }

    // s[channel][pixel]; bank = (4*lane8 + sub + 4*warp) mod 32 -> all distinct
    s[4 * lane8 + 0][p] = a0;
    s[4 * lane8 + 1][p] = a1;
    s[4 * lane8 + 2][p] = a2;
    s[4 * lane8 + 3][p] = a3;
    __syncthreads();

    // warp w writes channels w and w+16: 64 contiguous floats each (256B)
#pragma unroll
    for (int q = 0; q < 2; q++) {
        int cc = warp + q * 16;
        float* orow = out + (((b * C_ + cc) * H_) + i) * W_ + jt * GW_;
        orow[lane]      = s[cc][lane];
        orow[lane + 32] = s[cc][lane + 32];
    }
}

extern "C" void kernel_launch(void* const* d_in, const int* in_sizes, int n_in,
                              void* d_out, int out_size) {
    const float* input = (const float*)d_in[0];   // [8,32,256,256]
    const float* flow  = (const float*)d_in[1];   // [8,2,64,64]
    float* out = (float*)d_out;                   // [8,32,256,256]

    {
        int total = B_ * H_ * W_;
        coords_kernel<<<(total + 255) / 256, 256>>>(flow);
    }
    {
        dim3 grid(W_ / 32, H_, B_);
        dim3 block(32, 32);
        transpose_kernel<<<grid, block>>>(input);
    }
    {
        dim3 grid(W_ / GW_, H_, B_);
        gather_kernel<<<grid, 512>>>(out);
    }
}

// round 6
// speedup vs baseline: 1.6286x; 1.0020x over previous
#include <cuda_runtime.h>
#include <cuda_fp16.h>

#define B_ 8
#define C_ 32
#define H_ 256
#define W_ 256
#define FH_ 64
#define FW_ 64
#define P_ 25
#define HP_ 306   // H + 2*25

// Scratch: fp16 transposed input [B,H,W,C] (64B/pixel) + per-pixel coords
__device__ __align__(128) __half g_tin_h[B_ * H_ * W_ * C_];
__device__ float g_coords[B_ * H_ * W_ * 2];

// XLA:GPU lowers f32 divide to div.full.f32 (~2 ulp). The resize 'src'
// coordinate src = i*63/255 is the ONE place where that rounding error is
// amplified: it survives (src - floor(src)) undamped and is then scaled by
// 152.5 into the sample position. Bit-match XLA's division here. (R3->R4:
// rel_err 1.76e-3 -> 1.24e-4.) DO NOT replace with __fdiv_rn or fast div.
__device__ __forceinline__ float div_full(float a, float b) {
    float r;
    asm("div.full.f32 %0, %1, %2;" : "=f"(r) : "f"(a), "f"(b));
    return r;
}

__device__ __forceinline__ void cubic_w(float t, float w[4]) {
    const float A = -0.75f;
    float x;
    x = t + 1.0f; w[0] = ((A * x - 5.0f * A) * x + 8.0f * A) * x - 4.0f * A;
    x = t;        w[1] = ((A + 2.0f) * x - (A + 3.0f)) * x * x + 1.0f;
    x = 1.0f - t; w[2] = ((A + 2.0f) * x - (A + 3.0f)) * x * x + 1.0f;
    x = 2.0f - t; w[3] = ((A * x - 5.0f * A) * x + 8.0f * A) * x - 4.0f * A;
}

// ---------------------------------------------------------------------------
// Kernel 1: per-pixel sample coordinates (bicubic flow upsample + grid math)
// ---------------------------------------------------------------------------
__global__ void coords_kernel(const float* __restrict__ flow) {
    int idx = blockIdx.x * blockDim.x + threadIdx.x;
    if (idx >= B_ * H_ * W_) return;
    int j = idx & (W_ - 1);
    int i = (idx >> 8) & (H_ - 1);
    int b = idx >> 16;

    float sy = div_full((float)i * (float)(FH_ - 1), (float)(H_ - 1));
    float sx = div_full((float)j * (float)(FW_ - 1), (float)(W_ - 1));
    float fy0 = floorf(sy), fx0 = floorf(sx);
    float ty = sy - fy0, tx = sx - fx0;   // exact (Sterbenz)
    int iy0 = (int)fy0, ix0 = (int)fx0;
    float wy[4], wx[4];
    cubic_w(ty, wy);
    cubic_w(tx, wx);

    const float* f0 = flow + b * 2 * FH_ * FW_;   // channel 0: x-flow
    const float* f1 = f0 + FH_ * FW_;             // channel 1: y-flow

    int ry[4], rx[4];
#pragma unroll
    for (int m = 0; m < 4; m++) {
        int y = iy0 - 1 + m; ry[m] = min(max(y, 0), FH_ - 1);
        int x = ix0 - 1 + m; rx[m] = min(max(x, 0), FW_ - 1);
    }
    float accx = 0.0f, accy = 0.0f;
#pragma unroll
    for (int m = 0; m < 4; m++) {
        int rb = ry[m] * FW_;
#pragma unroll
        for (int n = 0; n < 4; n++) {
            float w = wy[m] * wx[n];
            int o = rb + rx[n];
            accx += w * __ldg(&f0[o]);
            accy += w * __ldg(&f1[o]);
        }
    }

    float gx256 = -1.0f + j * (2.0f / (float)(W_ - 1));
    float gy256 = -1.0f + i * (2.0f / (float)(H_ - 1));
    float gx306 = -1.0f + (j + P_) * (2.0f / (float)(HP_ - 1));
    float gy306 = -1.0f + (i + P_) * (2.0f / (float)(HP_ - 1));
    float xp = (accx - gx256 + gx306 + 1.0f) * (0.5f * (float)(HP_ - 1));
    float yp = (accy - gy256 + gy306 + 1.0f) * (0.5f * (float)(HP_ - 1));

    g_coords[idx * 2 + 0] = xp;
    g_coords[idx * 2 + 1] = yp;
}

// ---------------------------------------------------------------------------
// Kernel 2: transpose input [B,C,H,W] f32 -> [B,H,W,C] f16 (64B per pixel)
// ---------------------------------------------------------------------------
__global__ __launch_bounds__(1024) void transpose_kernel(const float* __restrict__ inp) {
    __shared__ float s[32][33];
    int b = blockIdx.z;
    int h = blockIdx.y;
    int w0 = blockIdx.x * 32;

    s[threadIdx.y][threadIdx.x] =
        inp[(((b * C_ + threadIdx.y) * H_) + h) * W_ + w0 + threadIdx.x];
    __syncthreads();
    g_tin_h[((b * H_ + h) * W_ + (w0 + threadIdx.y)) * C_ + threadIdx.x] =
        __float2half_rn(s[threadIdx.x][threadIdx.y]);
}

// ---------------------------------------------------------------------------
// Kernel 3: gather over 8x8 OUTPUT TILES (R6 change). Flow is smooth at the
// 64->256 upsample scale, so adjacent pixels' 4x4 tap footprints overlap
// ~70-90%. A 2D tile makes the block footprint ~160 texels (~10KB) -> L1-
// resident, capturing reuse in BOTH axes (the 64x1 strip wasted all vertical
// reuse). warp = 4 adjacent same-row pixels (8 lanes each, uint2 = 4 halfs).
// ---------------------------------------------------------------------------
#define TPX_ 8   // tile width (pixels)
#define TPY_ 8   // tile height
__global__ __launch_bounds__(512) void gather_kernel(float* __restrict__ out) {
    __shared__ float s[C_][TPX_ * TPY_ + 1];
    int b = blockIdx.z;
    int ty0 = (blockIdx.y) * TPY_;
    int tx0 = (blockIdx.x) * TPX_;
    int warp = threadIdx.x >> 5;         // 0..15
    int lane = threadIdx.x & 31;
    int sub = lane >> 3;                 // pixel-in-warp 0..3
    int lane8 = lane & 7;                // channel-group 0..7
    int p = warp * 4 + sub;              // pixel-in-tile 0..63
    int px = p & (TPX_ - 1);             // warp's 4 pixels: same row, adj x
    int py = p >> 3;
    int i = ty0 + py;
    int j = tx0 + px;

    int pidx = ((b * H_) + i) * W_ + j;
    float xp = __ldg(&g_coords[pidx * 2 + 0]);
    float yp = __ldg(&g_coords[pidx * 2 + 1]);

    float fx = floorf(xp), fy = floorf(yp);
    float tx = xp - fx, ty = yp - fy;
    int ix = (int)fx, iy = (int)fy;

    float a0 = 0.0f, a1 = 0.0f, a2 = 0.0f, a3 = 0.0f;

    bool dead = (iy + 2 < 0) | (iy - 1 >= HP_) | (ix + 2 < 0) | (ix - 1 >= HP_);
    if (!__all_sync(0xFFFFFFFFu, dead)) {
        float wx[4], wy[4];
        cubic_w(tx, wx);
        cubic_w(ty, wy);

        const __half* base = g_tin_h + (size_t)b * (H_ * W_ * C_) + lane8 * 4;
#pragma unroll
        for (int m = 0; m < 4; m++) {
            int yy = iy - 1 + m;
            if ((unsigned)yy < (unsigned)HP_) {
                int ys = min(max(yy - P_, 0), H_ - 1);
                const __half* row = base + ys * (W_ * C_);
                float wym = wy[m];
#pragma unroll
                for (int n = 0; n < 4; n++) {
                    int xx = ix - 1 + n;
                    if ((unsigned)xx < (unsigned)HP_) {
                        int xs = min(max(xx - P_, 0), W_ - 1);
                        uint2 v = __ldg((const uint2*)(row + xs * C_));
                        float2 f01 = __half22float2(*(const __half2*)&v.x);
                        float2 f23 = __half22float2(*(const __half2*)&v.y);
                        float w = wym * wx[n];
                        a0 += w * f01.x;
                        a1 += w * f01.y;
                        a2 += w * f23.x;
                        a3 += w * f23.y;
                    }
                }
            }
        }
    }

    // s[channel][pixel]; write bank = (4*lane8 + k + 4*warp + sub) mod 32 ->
    // distinct across lanes for each k. (65-stride padding.)
    s[4 * lane8 + 0][p] = a0;
    s[4 * lane8 + 1][p] = a1;
    s[4 * lane8 + 2][p] = a2;
    s[4 * lane8 + 3][p] = a3;
    __syncthreads();

    // warp w writes channels w and w+16; pixel q -> out row ty0+(q>>3), col
    // tx0+(q&7): 4x 32B segments per STG (sector-aligned, no waste).
#pragma unroll
    for (int qq = 0; qq < 2; qq++) {
        int cc = warp + qq * 16;
        const float* src = s[cc];
        float* obase = out + (((b * C_ + cc) * H_)) * W_;
#pragma unroll
        for (int half = 0; half < 2; half++) {
            int q = lane + half * 32;
            int oy = ty0 + (q >> 3);
            int ox = tx0 + (q & (TPX_ - 1));
            obase[oy * W_ + ox] = src[q];
        }
    }
}

extern "C" void kernel_launch(void* const* d_in, const int* in_sizes, int n_in,
                              void* d_out, int out_size) {
    const float* input = (const float*)d_in[0];   // [8,32,256,256]
    const float* flow  = (const float*)d_in[1];   // [8,2,64,64]
    float* out = (float*)d_out;                   // [8,32,256,256]

    {
        int total = B_ * H_ * W_;
        coords_kernel<<<(total + 255) / 256, 256>>>(flow);
    }
    {
        dim3 grid(W_ / 32, H_, B_);
        dim3 block(32, 32);
        transpose_kernel<<<grid, block>>>(input);
    }
    {
        dim3 grid(W_ / TPX_, H_ / TPY_, B_);
        gather_kernel<<<grid, 512>>>(out);
    }
}

// round 7
// speedup vs baseline: 2.9669x; 1.8217x over previous
#include <cuda_runtime.h>
#include <cuda_fp16.h>

#define B_ 8
#define C_ 32
#define H_ 256
#define W_ 256
#define FH_ 64
#define FW_ 64
#define P_ 25
#define HP_ 306   // H + 2*25

// Scratch: fp16 transposed input [B,H,W,C] (64B/pixel) + per-pixel coords
__device__ __align__(128) __half g_tin_h[B_ * H_ * W_ * C_];
__device__ float g_coords[B_ * H_ * W_ * 2];

// XLA:GPU lowers f32 divide to div.full.f32 (~2 ulp). The resize 'src'
// coordinate src = i*63/255 is the ONE place where that rounding error is
// amplified: it survives (src - floor(src)) undamped and is then scaled by
// 152.5 into the sample position. Bit-match XLA's division here. (R3->R4:
// rel_err 1.76e-3 -> 1.24e-4.) DO NOT replace with __fdiv_rn or fast div.
__device__ __forceinline__ float div_full(float a, float b) {
    float r;
    asm("div.full.f32 %0, %1, %2;" : "=f"(r) : "f"(a), "f"(b));
    return r;
}

__device__ __forceinline__ void cubic_w(float t, float w[4]) {
    const float A = -0.75f;
    float x;
    x = t + 1.0f; w[0] = ((A * x - 5.0f * A) * x + 8.0f * A) * x - 4.0f * A;
    x = t;        w[1] = ((A + 2.0f) * x - (A + 3.0f)) * x * x + 1.0f;
    x = 1.0f - t; w[2] = ((A + 2.0f) * x - (A + 3.0f)) * x * x + 1.0f;
    x = 2.0f - t; w[3] = ((A * x - 5.0f * A) * x + 8.0f * A) * x - 4.0f * A;
}

// ---------------------------------------------------------------------------
// Kernel 1: per-pixel sample coordinates (bicubic flow upsample + grid math)
// ---------------------------------------------------------------------------
__global__ void coords_kernel(const float* __restrict__ flow) {
    int idx = blockIdx.x * blockDim.x + threadIdx.x;
    if (idx >= B_ * H_ * W_) return;
    int j = idx & (W_ - 1);
    int i = (idx >> 8) & (H_ - 1);
    int b = idx >> 16;

    float sy = div_full((float)i * (float)(FH_ - 1), (float)(H_ - 1));
    float sx = div_full((float)j * (float)(FW_ - 1), (float)(W_ - 1));
    float fy0 = floorf(sy), fx0 = floorf(sx);
    float ty = sy - fy0, tx = sx - fx0;   // exact (Sterbenz)
    int iy0 = (int)fy0, ix0 = (int)fx0;
    float wy[4], wx[4];
    cubic_w(ty, wy);
    cubic_w(tx, wx);

    const float* f0 = flow + b * 2 * FH_ * FW_;   // channel 0: x-flow
    const float* f1 = f0 + FH_ * FW_;             // channel 1: y-flow

    int ry[4], rx[4];
#pragma unroll
    for (int m = 0; m < 4; m++) {
        int y = iy0 - 1 + m; ry[m] = min(max(y, 0), FH_ - 1);
        int x = ix0 - 1 + m; rx[m] = min(max(x, 0), FW_ - 1);
    }
    float accx = 0.0f, accy = 0.0f;
#pragma unroll
    for (int m = 0; m < 4; m++) {
        int rb = ry[m] * FW_;
#pragma unroll
        for (int n = 0; n < 4; n++) {
            float w = wy[m] * wx[n];
            int o = rb + rx[n];
            accx += w * __ldg(&f0[o]);
            accy += w * __ldg(&f1[o]);
        }
    }

    float gx256 = -1.0f + j * (2.0f / (float)(W_ - 1));
    float gy256 = -1.0f + i * (2.0f / (float)(H_ - 1));
    float gx306 = -1.0f + (j + P_) * (2.0f / (float)(HP_ - 1));
    float gy306 = -1.0f + (i + P_) * (2.0f / (float)(HP_ - 1));
    float xp = (accx - gx256 + gx306 + 1.0f) * (0.5f * (float)(HP_ - 1));
    float yp = (accy - gy256 + gy306 + 1.0f) * (0.5f * (float)(HP_ - 1));

    g_coords[idx * 2 + 0] = xp;
    g_coords[idx * 2 + 1] = yp;
}

// ---------------------------------------------------------------------------
// Kernel 2: transpose [B,C,H,W] f32 -> [B,H,W,C] f16. R7: vectorized store
// phase — each thread packs 4 channels of one pixel into a uint2 (STG.64,
// 256B contiguous per warp). 4 coalesced 128B loads per warp in load phase.
// ---------------------------------------------------------------------------
__global__ __launch_bounds__(256) void transpose_kernel(const float* __restrict__ inp) {
    __shared__ float s[32][33];
    int b = blockIdx.z;
    int h = blockIdx.y;
    int w0 = blockIdx.x * 32;
    int t = threadIdx.x;
    int lane = t & 31;
    int warp = t >> 5;   // 0..7

#pragma unroll
    for (int k = 0; k < 4; k++) {
        int c = warp + 8 * k;
        s[c][lane] = inp[(((b * C_ + c) * H_) + h) * W_ + w0 + lane];
    }
    __syncthreads();

    // thread -> (pixel = t>>3, channel group = t&7); LDS bank = 4*lane8+k+pix
    // (mod 32) distinct across the warp for each k -> conflict-free.
    int lane8 = t & 7;
    int pix = t >> 3;    // 0..31
    float f0 = s[4 * lane8 + 0][pix];
    float f1 = s[4 * lane8 + 1][pix];
    float f2 = s[4 * lane8 + 2][pix];
    float f3 = s[4 * lane8 + 3][pix];
    __half2 h01 = __floats2half2_rn(f0, f1);
    __half2 h23 = __floats2half2_rn(f2, f3);
    uint2 v;
    v.x = *(unsigned*)&h01;
    v.y = *(unsigned*)&h23;
    *(uint2*)(g_tin_h + ((size_t)((b * H_ + h) * W_ + w0 + pix)) * C_ + 4 * lane8) = v;
}

// ---------------------------------------------------------------------------
// Kernel 3: gather. R7: warp = 8 pixels, lane = 8 channels via ONE uint4
// (16B) per tap -> half the LDG instructions of R6, ~33% fewer instructions,
// 4 staged LDG.128s per m-row for MLP. 256-thr blocks (~4 blocks/SM -> 32
// warps/SM for latency hiding). No inter-pixel reuse exists (flow amplitude
// = +-152px >> 4px footprint; R6 finding), so layout is chosen purely for
// store coalescing: 64-px j-strips.
// ---------------------------------------------------------------------------
#define GPX_ 64   // pixels per block (8 warps * 8)
__global__ __launch_bounds__(256) void gather_kernel(float* __restrict__ out) {
    __shared__ float s[C_][GPX_ + 1];
    int b = blockIdx.z;
    int i = blockIdx.y;
    int j0 = blockIdx.x * GPX_;
    int warp = threadIdx.x >> 5;   // 0..7
    int lane = threadIdx.x & 31;
    int pix = lane >> 2;           // pixel-in-warp 0..7
    int lane4 = lane & 3;          // channel-quarter 0..3 (8 halfs each)
    int p = warp * 8 + pix;        // pixel-in-block 0..63
    int j = j0 + p;

    int pidx = ((b * H_) + i) * W_ + j;
    float xp = __ldg(&g_coords[pidx * 2 + 0]);
    float yp = __ldg(&g_coords[pidx * 2 + 1]);

    float fx = floorf(xp), fy = floorf(yp);
    float tx = xp - fx, ty = yp - fy;
    int ix = (int)fx, iy = (int)fy;

    float a0 = 0.f, a1 = 0.f, a2 = 0.f, a3 = 0.f;
    float a4 = 0.f, a5 = 0.f, a6 = 0.f, a7 = 0.f;

    bool dead = (iy + 2 < 0) | (iy - 1 >= HP_) | (ix + 2 < 0) | (ix - 1 >= HP_);
    if (!__all_sync(0xFFFFFFFFu, dead)) {
        float wx[4], wy[4];
        cubic_w(tx, wx);
        cubic_w(ty, wy);

        const __half* base = g_tin_h + (size_t)b * (H_ * W_ * C_) + lane4 * 8;
#pragma unroll
        for (int m = 0; m < 4; m++) {
            int yy = iy - 1 + m;
            if ((unsigned)yy < (unsigned)HP_) {
                int ys = min(max(yy - P_, 0), H_ - 1);
                const __half* row = base + ys * (W_ * C_);
                float wym = wy[m];
                uint4 v[4];
                bool val[4];
#pragma unroll
                for (int n = 0; n < 4; n++) {
                    int xx = ix - 1 + n;
                    val[n] = ((unsigned)xx < (unsigned)HP_);
                    int xs = min(max(xx - P_, 0), W_ - 1);
                    if (val[n]) v[n] = __ldg((const uint4*)(row + xs * C_));
                }
#pragma unroll
                for (int n = 0; n < 4; n++) {
                    if (val[n]) {
                        float w = wym * wx[n];
                        float2 f01 = __half22float2(*(const __half2*)&v[n].x);
                        float2 f23 = __half22float2(*(const __half2*)&v[n].y);
                        float2 f45 = __half22float2(*(const __half2*)&v[n].z);
                        float2 f67 = __half22float2(*(const __half2*)&v[n].w);
                        a0 += w * f01.x;  a1 += w * f01.y;
                        a2 += w * f23.x;  a3 += w * f23.y;
                        a4 += w * f45.x;  a5 += w * f45.y;
                        a6 += w * f67.x;  a7 += w * f67.y;
                    }
                }
            }
        }
    }

    // s[channel][pixel]; write bank = 8*lane4 + k + pix (+8*warp) mod 32:
    // 8*lane4 in {0,8,16,24}, pix 0..7 -> all 32 distinct. Conflict-free.
    float acc[8] = {a0, a1, a2, a3, a4, a5, a6, a7};
#pragma unroll
    for (int k = 0; k < 8; k++) s[8 * lane4 + k][p] = acc[k];
    __syncthreads();

    // warp w stores channels {w, w+8, w+16, w+24}: 64 contiguous floats each
    // (2 x 128B STG). Read bank = cc + q mod 32: conflict-free.
#pragma unroll
    for (int q = 0; q < 4; q++) {
        int cc = warp + q * 8;
        float* orow = out + (((b * C_ + cc) * H_) + i) * W_ + j0;
        orow[lane]      = s[cc][lane];
        orow[lane + 32] = s[cc][lane + 32];
    }
}

extern "C" void kernel_launch(void* const* d_in, const int* in_sizes, int n_in,
                              void* d_out, int out_size) {
    const float* input = (const float*)d_in[0];   // [8,32,256,256]
    const float* flow  = (const float*)d_in[1];   // [8,2,64,64]
    float* out = (float*)d_out;                   // [8,32,256,256]

    {
        int total = B_ * H_ * W_;
        coords_kernel<<<(total + 255) / 256, 256>>>(flow);
    }
    {
        dim3 grid(W_ / 32, H_, B_);
        transpose_kernel<<<grid, 256>>>(input);
    }
    {
        dim3 grid(W_ / GPX_, H_, B_);
        gather_kernel<<<grid, 256>>>(out);
    }
}

// round 8
// speedup vs baseline: 3.3131x; 1.1167x over previous
#include <cuda_runtime.h>
#include <cuda_fp16.h>

#define B_ 8
#define C_ 32
#define H_ 256
#define W_ 256
#define FH_ 64
#define FW_ 64
#define P_ 25
#define HP_ 306   // H + 2*25

// Scratch: fp16 transposed input [B,H,W,C] (64B/pixel) + per-pixel coords
__device__ __align__(128) __half g_tin_h[B_ * H_ * W_ * C_];
__device__ float g_coords[B_ * H_ * W_ * 2];

// XLA:GPU lowers f32 divide to div.full.f32 (~2 ulp). The resize 'src'
// coordinate src = i*63/255 is the ONE place where that rounding error is
// amplified: it survives (src - floor(src)) undamped and is then scaled by
// 152.5 into the sample position. Bit-match XLA's division here. (R3->R4:
// rel_err 1.76e-3 -> 1.24e-4.) DO NOT replace with __fdiv_rn or fast div.
__device__ __forceinline__ float div_full(float a, float b) {
    float r;
    asm("div.full.f32 %0, %1, %2;" : "=f"(r) : "f"(a), "f"(b));
    return r;
}

__device__ __forceinline__ void cubic_w(float t, float w[4]) {
    const float A = -0.75f;
    float x;
    x = t + 1.0f; w[0] = ((A * x - 5.0f * A) * x + 8.0f * A) * x - 4.0f * A;
    x = t;        w[1] = ((A + 2.0f) * x - (A + 3.0f)) * x * x + 1.0f;
    x = 1.0f - t; w[2] = ((A + 2.0f) * x - (A + 3.0f)) * x * x + 1.0f;
    x = 2.0f - t; w[3] = ((A * x - 5.0f * A) * x + 8.0f * A) * x - 4.0f * A;
}

// ---------------------------------------------------------------------------
// Kernel 1 (fused prep): blocks [0,16384) transpose [B,C,H,W] f32 ->
// [B,H,W,C] f16; blocks [16384,18432) compute per-pixel sample coords.
// Independent work, one launch -> coords hides inside transpose's mem time.
// ---------------------------------------------------------------------------
#define TR_BLOCKS_ (B_ * H_ * (W_ / 32))          // 16384
#define CO_BLOCKS_ ((B_ * H_ * W_) / 256)         // 2048

__global__ __launch_bounds__(256) void prep_kernel(const float* __restrict__ inp,
                                                   const float* __restrict__ flow) {
    __shared__ float s[32][33];
    int t = threadIdx.x;

    if (blockIdx.x < TR_BLOCKS_) {
        // ---- transpose part ----
        int bx = blockIdx.x;
        int w0 = (bx & 7) * 32;
        int h = (bx >> 3) & (H_ - 1);
        int b = bx >> 11;
        int lane = t & 31;
        int warp = t >> 5;   // 0..7

#pragma unroll
        for (int k = 0; k < 4; k++) {
            int c = warp + 8 * k;
            s[c][lane] = inp[(((b * C_ + c) * H_) + h) * W_ + w0 + lane];
        }
        __syncthreads();

        int lane8 = t & 7;
        int pix = t >> 3;    // 0..31
        float f0 = s[4 * lane8 + 0][pix];
        float f1 = s[4 * lane8 + 1][pix];
        float f2 = s[4 * lane8 + 2][pix];
        float f3 = s[4 * lane8 + 3][pix];
        __half2 h01 = __floats2half2_rn(f0, f1);
        __half2 h23 = __floats2half2_rn(f2, f3);
        uint2 v;
        v.x = *(unsigned*)&h01;
        v.y = *(unsigned*)&h23;
        *(uint2*)(g_tin_h + ((size_t)((b * H_ + h) * W_ + w0 + pix)) * C_ + 4 * lane8) = v;
    } else {
        // ---- coords part ----
        int idx = (blockIdx.x - TR_BLOCKS_) * 256 + t;
        int j = idx & (W_ - 1);
        int i = (idx >> 8) & (H_ - 1);
        int b = idx >> 16;

        float sy = div_full((float)i * (float)(FH_ - 1), (float)(H_ - 1));
        float sx = div_full((float)j * (float)(FW_ - 1), (float)(W_ - 1));
        float fy0 = floorf(sy), fx0 = floorf(sx);
        float ty = sy - fy0, tx = sx - fx0;   // exact (Sterbenz)
        int iy0 = (int)fy0, ix0 = (int)fx0;
        float wy[4], wx[4];
        cubic_w(ty, wy);
        cubic_w(tx, wx);

        const float* f0 = flow + b * 2 * FH_ * FW_;   // channel 0: x-flow
        const float* f1 = f0 + FH_ * FW_;             // channel 1: y-flow

        int ry[4], rx[4];
#pragma unroll
        for (int m = 0; m < 4; m++) {
            int y = iy0 - 1 + m; ry[m] = min(max(y, 0), FH_ - 1);
            int x = ix0 - 1 + m; rx[m] = min(max(x, 0), FW_ - 1);
        }
        float accx = 0.0f, accy = 0.0f;
#pragma unroll
        for (int m = 0; m < 4; m++) {
            int rb = ry[m] * FW_;
#pragma unroll
            for (int n = 0; n < 4; n++) {
                float w = wy[m] * wx[n];
                int o = rb + rx[n];
                accx += w * __ldg(&f0[o]);
                accy += w * __ldg(&f1[o]);
            }
        }

        float gx256 = -1.0f + j * (2.0f / (float)(W_ - 1));
        float gy256 = -1.0f + i * (2.0f / (float)(H_ - 1));
        float gx306 = -1.0f + (j + P_) * (2.0f / (float)(HP_ - 1));
        float gy306 = -1.0f + (i + P_) * (2.0f / (float)(HP_ - 1));
        float xp = (accx - gx256 + gx306 + 1.0f) * (0.5f * (float)(HP_ - 1));
        float yp = (accy - gy256 + gy306 + 1.0f) * (0.5f * (float)(HP_ - 1));

        g_coords[idx * 2 + 0] = xp;
        g_coords[idx * 2 + 1] = yp;
    }
}

// ---------------------------------------------------------------------------
// Kernel 2: gather. warp = 8 pixels, lane = 8 channels (one uint4 per tap).
// R8: x-row accumulated in HFMA2 (fp16 weights), row sum converted once and
// combined across rows in f32 -> ~32 math instr/row vs ~68. Issue-bound
// kernel (R7 finding): instruction count converts ~1:1 to time.
// ---------------------------------------------------------------------------
#define GPX_ 64   // pixels per block (8 warps * 8)
__global__ __launch_bounds__(256) void gather_kernel(float* __restrict__ out) {
    __shared__ float s[C_][GPX_ + 1];
    int b = blockIdx.z;
    int i = blockIdx.y;
    int j0 = blockIdx.x * GPX_;
    int warp = threadIdx.x >> 5;   // 0..7
    int lane = threadIdx.x & 31;
    int pix = lane >> 2;           // pixel-in-warp 0..7
    int lane4 = lane & 3;          // channel-quarter 0..3 (8 halfs each)
    int p = warp * 8 + pix;        // pixel-in-block 0..63
    int j = j0 + p;

    int pidx = ((b * H_) + i) * W_ + j;
    float xp = __ldg(&g_coords[pidx * 2 + 0]);
    float yp = __ldg(&g_coords[pidx * 2 + 1]);

    float fx = floorf(xp), fy = floorf(yp);
    float tx = xp - fx, ty = yp - fy;
    int ix = (int)fx, iy = (int)fy;

    float a0 = 0.f, a1 = 0.f, a2 = 0.f, a3 = 0.f;
    float a4 = 0.f, a5 = 0.f, a6 = 0.f, a7 = 0.f;

    bool dead = (iy + 2 < 0) | (iy - 1 >= HP_) | (ix + 2 < 0) | (ix - 1 >= HP_);
    if (!__all_sync(0xFFFFFFFFu, dead)) {
        float wx[4], wy[4];
        cubic_w(tx, wx);
        cubic_w(ty, wy);
        __half2 wxh[4];
#pragma unroll
        for (int n = 0; n < 4; n++) wxh[n] = __float2half2_rn(wx[n]);

        const __half* base = g_tin_h + (size_t)b * (H_ * W_ * C_) + lane4 * 8;
#pragma unroll
        for (int m = 0; m < 4; m++) {
            int yy = iy - 1 + m;
            if ((unsigned)yy < (unsigned)HP_) {
                int ys = min(max(yy - P_, 0), H_ - 1);
                const __half* row = base + ys * (W_ * C_);
                float wym = wy[m];
                uint4 v[4];
                bool val[4];
#pragma unroll
                for (int n = 0; n < 4; n++) {
                    int xx = ix - 1 + n;
                    val[n] = ((unsigned)xx < (unsigned)HP_);
                    int xs = min(max(xx - P_, 0), W_ - 1);
                    if (val[n]) v[n] = __ldg((const uint4*)(row + xs * C_));
                }
                __half2 r0 = __float2half2_rn(0.f), r1 = r0, r2 = r0, r3 = r0;
#pragma unroll
                for (int n = 0; n < 4; n++) {
                    if (val[n]) {
                        r0 = __hfma2(*(const __half2*)&v[n].x, wxh[n], r0);
                        r1 = __hfma2(*(const __half2*)&v[n].y, wxh[n], r1);
                        r2 = __hfma2(*(const __half2*)&v[n].z, wxh[n], r2);
                        r3 = __hfma2(*(const __half2*)&v[n].w, wxh[n], r3);
                    }
                }
                float2 f01 = __half22float2(r0);
                float2 f23 = __half22float2(r1);
                float2 f45 = __half22float2(r2);
                float2 f67 = __half22float2(r3);
                a0 += wym * f01.x;  a1 += wym * f01.y;
                a2 += wym * f23.x;  a3 += wym * f23.y;
                a4 += wym * f45.x;  a5 += wym * f45.y;
                a6 += wym * f67.x;  a7 += wym * f67.y;
            }
        }
    }

    // s[channel][pixel]; write bank = 8*lane4 + k + pix (+8*warp) mod 32:
    // all 32 distinct -> conflict-free.
    float acc[8] = {a0, a1, a2, a3, a4, a5, a6, a7};
#pragma unroll
    for (int k = 0; k < 8; k++) s[8 * lane4 + k][p] = acc[k];
    __syncthreads();

    // warp w stores channels {w, w+8, w+16, w+24}: 64 contiguous floats each
    // (2 x 128B STG). Read bank = cc + q mod 32: conflict-free.
#pragma unroll
    for (int q = 0; q < 4; q++) {
        int cc = warp + q * 8;
        float* orow = out + (((b * C_ + cc) * H_) + i) * W_ + j0;
        orow[lane]      = s[cc][lane];
        orow[lane + 32] = s[cc][lane + 32];
    }
}

extern "C" void kernel_launch(void* const* d_in, const int* in_sizes, int n_in,
                              void* d_out, int out_size) {
    const float* input = (const float*)d_in[0];   // [8,32,256,256]
    const float* flow  = (const float*)d_in[1];   // [8,2,64,64]
    float* out = (float*)d_out;                   // [8,32,256,256]

    prep_kernel<<<TR_BLOCKS_ + CO_BLOCKS_, 256>>>(input, flow);
    {
        dim3 grid(W_ / GPX_, H_, B_);
        gather_kernel<<<grid, 256>>>(out);
    }
}